// round 2
// baseline (speedup 1.0000x reference)
#include <cuda_runtime.h>

#define BB 8
#define NN 512
#define NROWS (BB * NN)   // 4096

// ---------------- scratch (device globals; no allocation allowed) ----------
__device__ float g_h[NROWS * 128];     // node features h
__device__ float g_ui[NROWS * 64];     // coords @ aw0[0:3] + ab0
__device__ float g_uj[NROWS * 64];     // coords @ aw0[3:6]
__device__ float g_upd[NROWS * 259];   // [h | coords | V]
__device__ float g_hn[NROWS * 128];    // h_next before maxpool

// ============================================================================
// Kernel 1: per-node feature MLP + precompute ui/uj. One thread per row.
// ============================================================================
__global__ void k_feat(const float* __restrict__ coords,
                       const float* __restrict__ fw0, const float* __restrict__ fb0,
                       const float* __restrict__ fw1, const float* __restrict__ fb1,
                       const float* __restrict__ aw0, const float* __restrict__ ab0)
{
    int row = blockIdx.x * blockDim.x + threadIdx.x;
    if (row >= NROWS) return;
    float c0 = coords[row * 3 + 0];
    float c1 = coords[row * 3 + 1];
    float c2 = coords[row * 3 + 2];

    float h0[64];
#pragma unroll
    for (int k = 0; k < 64; k++) {
        float v = fb0[k] + c0 * fw0[k] + c1 * fw0[64 + k] + c2 * fw0[128 + k];
        h0[k] = fmaxf(v, 0.f);
        // adjacency layer-0 split: ui gets ab0 folded in
        float u = ab0[k] + c0 * aw0[k] + c1 * aw0[64 + k] + c2 * aw0[128 + k];
        g_ui[row * 64 + k] = u;
        float w = c0 * aw0[192 + k] + c1 * aw0[256 + k] + c2 * aw0[320 + k];
        g_uj[row * 64 + k] = w;
    }

    // h = relu(h0 @ fw1 + fb1), fw1 is (64,128) row-major
    for (int cb = 0; cb < 128; cb += 4) {
        float ax = fb1[cb + 0], ay = fb1[cb + 1], az = fb1[cb + 2], aw = fb1[cb + 3];
#pragma unroll
        for (int k = 0; k < 64; k++) {
            float4 w = *(const float4*)&fw1[k * 128 + cb];
            ax += h0[k] * w.x; ay += h0[k] * w.y;
            az += h0[k] * w.z; aw += h0[k] * w.w;
        }
        ax = fmaxf(ax, 0.f); ay = fmaxf(ay, 0.f);
        az = fmaxf(az, 0.f); aw = fmaxf(aw, 0.f);
        float4 o = make_float4(ax, ay, az, aw);
        *(float4*)&g_h[row * 128 + cb] = o;
        g_upd[row * 259 + cb + 0] = ax;
        g_upd[row * 259 + cb + 1] = ay;
        g_upd[row * 259 + cb + 2] = az;
        g_upd[row * 259 + cb + 3] = aw;
    }
    g_upd[row * 259 + 128] = c0;
    g_upd[row * 259 + 129] = c1;
    g_upd[row * 259 + 130] = c2;
}

// ============================================================================
// Kernel 2: fused adjacency MLP + aggregation.
// grid = 1024 CTAs (4 i-rows each), block = 256.
// Per (b, i-tile): for each j-tile of 128:
//   a1[j][k] = relu(ui[i][k] + uj[j][k])        (layer 0, precomputed split)
//   a2 = relu(a1 @ aw1 + ab1); A = relu(a2 . aw2 + ab2)   (fused GEMM+reduce)
//   V[i] += sum_j A[j] * h[j]                    (never materialize A globally)
// ============================================================================
#define A1P 66   // a1 smem row pad (bank-conflict free for 4-way jg reads)
#define AWP 68   // aw1 smem row pad (keeps float4 alignment)
#define SMEM_ADJ ((64 * AWP + 128 * A1P + 128 * 64 + 4 * 64 + 4 * 128 + 128) * 4)

__global__ __launch_bounds__(256, 2) void k_adj(
    const float* __restrict__ aw1, const float* __restrict__ ab1,
    const float* __restrict__ aw2, const float* __restrict__ ab2)
{
    extern __shared__ float sm[];
    float* s_aw1 = sm;                       // 64 * AWP
    float* s_a1  = s_aw1 + 64 * AWP;         // 128 * A1P
    float* s_uj  = s_a1 + 128 * A1P;         // 128 * 64
    float* s_ui  = s_uj + 128 * 64;          // 4 * 64
    float* s_A   = s_ui + 4 * 64;            // 4 * 128
    float* s_ab1 = s_A + 4 * 128;            // 64
    float* s_aw2 = s_ab1 + 64;               // 64

    const int tid = threadIdx.x;
    const int b  = blockIdx.x >> 7;
    const int i0 = (blockIdx.x & 127) << 2;

    for (int idx = tid; idx < 4096; idx += 256) {
        int k = idx >> 6, kk = idx & 63;
        s_aw1[k * AWP + kk] = aw1[idx];
    }
    {
        int it = tid >> 6, k = tid & 63;
        s_ui[tid] = g_ui[(b * NN + i0 + it) * 64 + k];
    }
    if (tid < 64) { s_ab1[tid] = ab1[tid]; s_aw2[tid] = aw2[tid]; }
    const float ab2v = ab2[0];

    const int kkg = tid & 7;       // 8 kk-groups of 8
    const int jg  = tid >> 3;      // 32 j-groups of 4
    const int c    = tid & 127;    // V channel
    const int half = tid >> 7;     // j-half for phase C
    float Vacc[4] = {0.f, 0.f, 0.f, 0.f};

    __syncthreads();

    for (int jt = 0; jt < 4; jt++) {
        const int jbase = jt * 128;
        // stage uj tile
        {
            const float4* src = (const float4*)&g_uj[(b * NN + jbase) * 64];
            float4* dst = (float4*)s_uj;
            for (int idx = tid; idx < 2048; idx += 256) dst[idx] = src[idx];
        }
        __syncthreads();

        for (int it = 0; it < 4; it++) {
            // Phase A: a1 tile
            for (int idx = tid; idx < 8192; idx += 256) {
                int j = idx >> 6, k = idx & 63;
                s_a1[j * A1P + k] = fmaxf(s_ui[it * 64 + k] + s_uj[idx], 0.f);
            }
            __syncthreads();

            // Phase B: (128x64) @ (64x64) GEMM, 4j x 8kk microtile per thread
            float acc[4][8];
#pragma unroll
            for (int x = 0; x < 4; x++)
#pragma unroll
                for (int q = 0; q < 8; q++) acc[x][q] = 0.f;

            const float* a1base = &s_a1[jg * 4 * A1P];
            const float* wbase  = &s_aw1[kkg * 8];
#pragma unroll 4
            for (int k = 0; k < 64; k++) {
                float4 w0 = *(const float4*)(wbase + k * AWP);
                float4 w1 = *(const float4*)(wbase + k * AWP + 4);
                float av[4];
#pragma unroll
                for (int x = 0; x < 4; x++) av[x] = a1base[x * A1P + k];
#pragma unroll
                for (int x = 0; x < 4; x++) {
                    acc[x][0] += av[x] * w0.x;
                    acc[x][1] += av[x] * w0.y;
                    acc[x][2] += av[x] * w0.z;
                    acc[x][3] += av[x] * w0.w;
                    acc[x][4] += av[x] * w1.x;
                    acc[x][5] += av[x] * w1.y;
                    acc[x][6] += av[x] * w1.z;
                    acc[x][7] += av[x] * w1.w;
                }
            }
            // epilogue: relu(a2) . aw2, shuffle-reduce across the 8 kk-groups
#pragma unroll
            for (int jj = 0; jj < 4; jj++) {
                float p = 0.f;
#pragma unroll
                for (int q = 0; q < 8; q++) {
                    int kk = kkg * 8 + q;
                    p += fmaxf(acc[jj][q] + s_ab1[kk], 0.f) * s_aw2[kk];
                }
                p += __shfl_xor_sync(0xffffffffu, p, 1);
                p += __shfl_xor_sync(0xffffffffu, p, 2);
                p += __shfl_xor_sync(0xffffffffu, p, 4);
                if (kkg == 0)
                    s_A[it * 128 + jg * 4 + jj] = fmaxf(p + ab2v, 0.f);
            }
            __syncthreads();
        }

        // Phase C: V accumulation against h tile (L2-resident)
        {
            const float* hp = &g_h[(size_t)(b * NN + jbase + half * 64) * 128 + c];
#pragma unroll 4
            for (int jj = 0; jj < 64; jj++) {
                float hv = hp[jj * 128];
#pragma unroll
                for (int it = 0; it < 4; it++)
                    Vacc[it] += s_A[it * 128 + half * 64 + jj] * hv;
            }
        }
        __syncthreads();
    }

    // combine the two j-halves and write V into updates[:, 131:259]
    if (half == 1) {
#pragma unroll
        for (int it = 0; it < 4; it++) s_A[it * 128 + c] = Vacc[it];
    }
    __syncthreads();
    if (half == 0) {
#pragma unroll
        for (int it = 0; it < 4; it++) {
            float v = Vacc[it] + s_A[it * 128 + c];
            g_upd[(size_t)(b * NN + i0 + it) * 259 + 131 + c] = v;
        }
    }
}

// ============================================================================
// Kernel 3: update MLP (259 -> 256 -> 128), 32 rows per CTA, 128 CTAs.
// ============================================================================
#define SMEM_UPD (2 * 32 * 260 * 4)

__global__ __launch_bounds__(256, 2) void k_upd(
    const float* __restrict__ uw0, const float* __restrict__ ub0,
    const float* __restrict__ uw1, const float* __restrict__ ub1)
{
    extern __shared__ float sm[];
    float* s_upd = sm;             // 32 * 260
    float* s_mid = sm + 32 * 260;  // 32 * 260

    const int tid = threadIdx.x;
    const int r0 = blockIdx.x * 32;

    for (int idx = tid; idx < 32 * 259; idx += 256) {
        int r = idx / 259, cc = idx - r * 259;
        s_upd[r * 260 + cc] = g_upd[(size_t)(r0 + r) * 259 + cc];
    }
    __syncthreads();

    const int mg = tid & 31;   // 32 groups over mid-dim
    const int rg = tid >> 5;   // 8 groups over rows (4 rows each)

    // GEMM1: (32x259) @ (259x256)
    {
        float acc[4][8];
#pragma unroll
        for (int x = 0; x < 4; x++)
#pragma unroll
            for (int q = 0; q < 8; q++) acc[x][q] = 0.f;

        for (int rr = 0; rr < 259; rr++) {
            float4 w0 = *(const float4*)&uw0[rr * 256 + mg * 8];
            float4 w1 = *(const float4*)&uw0[rr * 256 + mg * 8 + 4];
            float a0 = s_upd[(rg * 4 + 0) * 260 + rr];
            float a1 = s_upd[(rg * 4 + 1) * 260 + rr];
            float a2 = s_upd[(rg * 4 + 2) * 260 + rr];
            float a3 = s_upd[(rg * 4 + 3) * 260 + rr];
            float av[4] = {a0, a1, a2, a3};
#pragma unroll
            for (int x = 0; x < 4; x++) {
                acc[x][0] += av[x] * w0.x; acc[x][1] += av[x] * w0.y;
                acc[x][2] += av[x] * w0.z; acc[x][3] += av[x] * w0.w;
                acc[x][4] += av[x] * w1.x; acc[x][5] += av[x] * w1.y;
                acc[x][6] += av[x] * w1.z; acc[x][7] += av[x] * w1.w;
            }
        }
#pragma unroll
        for (int x = 0; x < 4; x++) {
#pragma unroll
            for (int q = 0; q < 8; q++) {
                s_mid[(rg * 4 + x) * 260 + mg * 8 + q] =
                    fmaxf(acc[x][q] + ub0[mg * 8 + q], 0.f);
            }
        }
    }
    __syncthreads();

    // GEMM2: (32x256) @ (256x128)
    {
        const int cg = tid & 31;  // 32 groups of 4 output channels
        float acc[4][4];
#pragma unroll
        for (int x = 0; x < 4; x++)
#pragma unroll
            for (int q = 0; q < 4; q++) acc[x][q] = 0.f;

        for (int mm = 0; mm < 256; mm++) {
            float4 w = *(const float4*)&uw1[mm * 128 + cg * 4];
            float av[4];
#pragma unroll
            for (int x = 0; x < 4; x++) av[x] = s_mid[(rg * 4 + x) * 260 + mm];
#pragma unroll
            for (int x = 0; x < 4; x++) {
                acc[x][0] += av[x] * w.x; acc[x][1] += av[x] * w.y;
                acc[x][2] += av[x] * w.z; acc[x][3] += av[x] * w.w;
            }
        }
#pragma unroll
        for (int x = 0; x < 4; x++) {
            float4 o;
            o.x = fmaxf(acc[x][0] + ub1[cg * 4 + 0], 0.f);
            o.y = fmaxf(acc[x][1] + ub1[cg * 4 + 1], 0.f);
            o.z = fmaxf(acc[x][2] + ub1[cg * 4 + 2], 0.f);
            o.w = fmaxf(acc[x][3] + ub1[cg * 4 + 3], 0.f);
            *(float4*)&g_hn[(size_t)(r0 + rg * 4 + x) * 128 + cg * 4] = o;
        }
    }
}

// ============================================================================
// Kernel 4: maxpool over N. One thread per (b, c).
// ============================================================================
__global__ void k_pool(float* __restrict__ out)
{
    int t = blockIdx.x * blockDim.x + threadIdx.x;  // 1024 threads
    int b = t >> 7, c = t & 127;
    float m = -3.4e38f;
    for (int n = 0; n < NN; n++)
        m = fmaxf(m, g_hn[(size_t)(b * NN + n) * 128 + c]);
    out[b * 128 + c] = m;
}

// ============================================================================
extern "C" void kernel_launch(void* const* d_in, const int* in_sizes, int n_in,
                              void* d_out, int out_size)
{
    const float* coords = (const float*)d_in[0];
    const float* fw0 = (const float*)d_in[1];
    const float* fb0 = (const float*)d_in[2];
    const float* fw1 = (const float*)d_in[3];
    const float* fb1 = (const float*)d_in[4];
    const float* aw0 = (const float*)d_in[5];
    const float* ab0 = (const float*)d_in[6];
    const float* aw1 = (const float*)d_in[7];
    const float* ab1 = (const float*)d_in[8];
    const float* aw2 = (const float*)d_in[9];
    const float* ab2 = (const float*)d_in[10];
    const float* uw0 = (const float*)d_in[11];
    const float* ub0 = (const float*)d_in[12];
    const float* uw1 = (const float*)d_in[13];
    const float* ub1 = (const float*)d_in[14];
    float* out = (float*)d_out;

    cudaFuncSetAttribute(k_adj, cudaFuncAttributeMaxDynamicSharedMemorySize, SMEM_ADJ);
    cudaFuncSetAttribute(k_upd, cudaFuncAttributeMaxDynamicSharedMemorySize, SMEM_UPD);

    k_feat<<<32, 128>>>(coords, fw0, fb0, fw1, fb1, aw0, ab0);
    k_adj<<<NROWS / 4, 256, SMEM_ADJ>>>(aw1, ab1, aw2, ab2);
    k_upd<<<NROWS / 32, 256, SMEM_UPD>>>(uw0, ub0, uw1, ub1);
    k_pool<<<4, 256>>>(out);
}

// round 5
// speedup vs baseline: 1.7596x; 1.7596x over previous
#include <cuda_runtime.h>
#include <cstdint>

#define BB 8
#define NN 512
#define NROWS (BB * NN)   // 4096

// ---------------- scratch (device globals; no allocation allowed) ----------
__device__ float g_h[NROWS * 128];
__device__ float g_ui[NROWS * 64];
__device__ float g_uj[NROWS * 64];
__device__ float g_upd[NROWS * 259];
__device__ float g_hn[NROWS * 128];
__device__ unsigned short g_wh[64 * 64];   // aw1^T hi bf16, [kk][k]
__device__ unsigned short g_wl[64 * 64];   // aw1^T lo bf16, [kk][k]

// ---------------- helpers ---------------------------------------------------
__device__ __forceinline__ uint32_t smem_u32(const void* p) {
    uint32_t a;
    asm("{ .reg .u64 t; cvta.to.shared.u64 t, %1; cvt.u32.u64 %0, t; }"
        : "=r"(a) : "l"(p));
    return a;
}
// r[31:16] = bf16(hi), r[15:0] = bf16(lo)
__device__ __forceinline__ uint32_t pack_bf16x2(float hi, float lo) {
    uint32_t r;
    asm("cvt.rn.bf16x2.f32 %0, %1, %2;" : "=r"(r) : "f"(hi), "f"(lo));
    return r;
}
__device__ __forceinline__ void ldsm_x4(uint32_t (&r)[4], uint32_t addr) {
    asm volatile("ldmatrix.sync.aligned.m8n8.x4.shared.b16 {%0,%1,%2,%3}, [%4];"
        : "=r"(r[0]), "=r"(r[1]), "=r"(r[2]), "=r"(r[3]) : "r"(addr));
}
// NON-transposed x2: B stored [n][k] (k contiguous) is col-major KxN, which is
// exactly the row.col B-fragment layout when addresses index the n-rows.
__device__ __forceinline__ void ldsm_x2(uint32_t (&r)[2], uint32_t addr) {
    asm volatile("ldmatrix.sync.aligned.m8n8.x2.shared.b16 {%0,%1}, [%2];"
        : "=r"(r[0]), "=r"(r[1]) : "r"(addr));
}
__device__ __forceinline__ void mma_bf16(float (&d)[4], const uint32_t (&a)[4],
                                         const uint32_t (&b)[2]) {
    asm volatile(
        "mma.sync.aligned.m16n8k16.row.col.f32.bf16.bf16.f32 "
        "{%0,%1,%2,%3}, {%4,%5,%6,%7}, {%8,%9}, {%0,%1,%2,%3};"
        : "+f"(d[0]), "+f"(d[1]), "+f"(d[2]), "+f"(d[3])
        : "r"(a[0]), "r"(a[1]), "r"(a[2]), "r"(a[3]), "r"(b[0]), "r"(b[1]));
}

// ============================================================================
// Kernel 0: split aw1 (transposed) into bf16 hi/lo, layout [kk][k]
// ============================================================================
__global__ void k_prep(const float* __restrict__ aw1) {
    int idx = blockIdx.x * 256 + threadIdx.x;
    if (idx >= 4096) return;
    int kk = idx & 63, k = idx >> 6;
    float w = aw1[k * 64 + kk];
    uint32_t hp = pack_bf16x2(0.f, w);
    float whf = __uint_as_float(hp << 16);
    uint32_t lp = pack_bf16x2(0.f, w - whf);
    g_wh[kk * 64 + k] = (unsigned short)(hp & 0xffffu);
    g_wl[kk * 64 + k] = (unsigned short)(lp & 0xffffu);
}

// ============================================================================
// Kernel 1: per-node feature MLP + ui/uj precompute
// ============================================================================
__global__ void k_feat(const float* __restrict__ coords,
                       const float* __restrict__ fw0, const float* __restrict__ fb0,
                       const float* __restrict__ fw1, const float* __restrict__ fb1,
                       const float* __restrict__ aw0, const float* __restrict__ ab0)
{
    int row = blockIdx.x * blockDim.x + threadIdx.x;
    if (row >= NROWS) return;
    float c0 = coords[row * 3 + 0];
    float c1 = coords[row * 3 + 1];
    float c2 = coords[row * 3 + 2];

    float h0[64];
#pragma unroll
    for (int k = 0; k < 64; k++) {
        float v = fb0[k] + c0 * fw0[k] + c1 * fw0[64 + k] + c2 * fw0[128 + k];
        h0[k] = fmaxf(v, 0.f);
        float u = ab0[k] + c0 * aw0[k] + c1 * aw0[64 + k] + c2 * aw0[128 + k];
        g_ui[row * 64 + k] = u;
        float w = c0 * aw0[192 + k] + c1 * aw0[256 + k] + c2 * aw0[320 + k];
        g_uj[row * 64 + k] = w;
    }

    for (int cb = 0; cb < 128; cb += 4) {
        float ax = fb1[cb + 0], ay = fb1[cb + 1], az = fb1[cb + 2], aw = fb1[cb + 3];
#pragma unroll
        for (int k = 0; k < 64; k++) {
            float4 w = *(const float4*)&fw1[k * 128 + cb];
            ax += h0[k] * w.x; ay += h0[k] * w.y;
            az += h0[k] * w.z; aw += h0[k] * w.w;
        }
        ax = fmaxf(ax, 0.f); ay = fmaxf(ay, 0.f);
        az = fmaxf(az, 0.f); aw = fmaxf(aw, 0.f);
        *(float4*)&g_h[row * 128 + cb] = make_float4(ax, ay, az, aw);
        g_upd[row * 259 + cb + 0] = ax;
        g_upd[row * 259 + cb + 1] = ay;
        g_upd[row * 259 + cb + 2] = az;
        g_upd[row * 259 + cb + 3] = aw;
    }
    g_upd[row * 259 + 128] = c0;
    g_upd[row * 259 + 129] = c1;
    g_upd[row * 259 + 130] = c2;
}

// ============================================================================
// Kernel 2: HMMA (mma.sync bf16 split-fp32) fused adjacency + aggregation.
// CTA = (b, 8 i-rows). grid 512, 256 threads (8 warps).
// ============================================================================
#define TSTR 144                 // bf16 tile row stride, bytes (72 halves)
#define UJS  66                  // uj smem row stride, floats
#define OFF_A1H  0               // 128*144 = 18432
#define OFF_A1L  18432           // 18432
#define OFF_WH   36864           // 64*144 = 9216
#define OFF_WL   46080           // 9216
#define OFF_UJ   55296           // 128*66*4 = 33792
#define OFF_UI   89088           // 8*64*4 = 2048
#define OFF_A    91136           // 8*128*4 = 4096
#define OFF_AB1  95232           // 256
#define OFF_AW2  95488           // 256
#define SMEM_ADJ 95744

__global__ void __launch_bounds__(256, 2) k_adj(
    const float* __restrict__ ab1, const float* __restrict__ aw2,
    const float* __restrict__ ab2)
{
    extern __shared__ char smem[];
    const uint32_t smb = smem_u32(smem);
    float* s_uj  = (float*)(smem + OFF_UJ);
    float* s_ui  = (float*)(smem + OFF_UI);
    float* s_A   = (float*)(smem + OFF_A);
    float* s_ab1 = (float*)(smem + OFF_AB1);
    float* s_aw2 = (float*)(smem + OFF_AW2);

    const int tid  = threadIdx.x;
    const int wid  = tid >> 5;
    const int lane = tid & 31;
    const int b    = blockIdx.x >> 6;
    const int i0   = (blockIdx.x & 63) << 3;

    // stage w hi/lo into padded smem tiles ([kk][k], 144B row stride)
    {
        const uint32_t* wh32 = (const uint32_t*)g_wh;
        const uint32_t* wl32 = (const uint32_t*)g_wl;
        for (int idx = tid; idx < 2048; idx += 256) {
            int kk = idx >> 5, kp = idx & 31;
            uint32_t off = (uint32_t)(kk * TSTR + kp * 4);
            *(uint32_t*)(smem + OFF_WH + off) = wh32[idx];
            *(uint32_t*)(smem + OFF_WL + off) = wl32[idx];
        }
    }
    for (int idx = tid; idx < 512; idx += 256)
        s_ui[idx] = g_ui[(size_t)(b * NN + i0 + (idx >> 6)) * 64 + (idx & 63)];
    if (tid < 64) { s_ab1[tid] = ab1[tid]; s_aw2[tid] = aw2[tid]; }
    const float ab2v = ab2[0];

    // per-thread fragment addressing
    const int m0 = wid * 16;                         // warp's j-row base
    const uint32_t a_row = (uint32_t)(m0 + (lane & 15));
    const uint32_t a_koff = (uint32_t)((lane >> 4) * 8);
    const uint32_t addrAh = smb + OFF_A1H + a_row * TSTR + a_koff * 2;
    const uint32_t addrAl = smb + OFF_A1L + a_row * TSTR + a_koff * 2;
    // B (non-trans x2): threads 0-7 -> n-rows 0-7 of k0 half, 8-15 -> k8 half
    const uint32_t b_nrow = (uint32_t)(lane & 7);
    const uint32_t b_koff = (uint32_t)(((lane >> 3) & 1) * 8);
    const uint32_t addrWh = smb + OFF_WH + b_nrow * TSTR + b_koff * 2;
    const uint32_t addrWl = smb + OFF_WL + b_nrow * TSTR + b_koff * 2;

    // phase-A addressing
    const int jrow = tid >> 1;
    const int kh   = (tid & 1) * 32;

    // V-phase addressing
    const int c    = tid & 127;
    const int half = tid >> 7;

    float Vacc[4] = {0.f, 0.f, 0.f, 0.f};

    __syncthreads();

    for (int jt = 0; jt < 4; jt++) {
        __syncthreads();
        // stage uj tile (128 x 64 floats, padded stride 66)
        {
            const float2* src = (const float2*)(g_uj + (size_t)(b * NN + jt * 128) * 64);
            for (int idx = tid; idx < 4096; idx += 256) {
                int r = idx >> 5, c2 = idx & 31;
                *(float2*)&s_uj[r * UJS + c2 * 2] = src[idx];
            }
        }
        __syncthreads();

        for (int i = 0; i < 8; i++) {
            // ---- phase A: split-bf16 a1 tile (relu(ui+uj)) ----
            {
                const float2* uj2 = (const float2*)(s_uj + jrow * UJS + kh);
                const float2* ui2 = (const float2*)(s_ui + i * 64 + kh);
                char* ah = smem + OFF_A1H + jrow * TSTR + kh * 2;
                char* al = smem + OFF_A1L + jrow * TSTR + kh * 2;
#pragma unroll
                for (int q = 0; q < 16; q++) {
                    float2 a = uj2[q];
                    float2 u = ui2[q];
                    float x0 = fmaxf(a.x + u.x, 0.f);
                    float x1 = fmaxf(a.y + u.y, 0.f);
                    uint32_t hi = pack_bf16x2(x1, x0);
                    float l0 = x0 - __uint_as_float(hi << 16);
                    float l1 = x1 - __uint_as_float(hi & 0xffff0000u);
                    uint32_t lo = pack_bf16x2(l1, l0);
                    *(uint32_t*)(ah + q * 4) = hi;
                    *(uint32_t*)(al + q * 4) = lo;
                }
            }
            __syncthreads();

            // ---- HMMA: a2 = a1h@wh + a1h@wl + a1l@wh ----
            float acc[8][4];
#pragma unroll
            for (int n = 0; n < 8; n++)
#pragma unroll
                for (int x = 0; x < 4; x++) acc[n][x] = 0.f;

#pragma unroll
            for (int k0 = 0; k0 < 4; k0++) {
                uint32_t Ah[4], Al[4];
                ldsm_x4(Ah, addrAh + k0 * 32);
                ldsm_x4(Al, addrAl + k0 * 32);
#pragma unroll
                for (int n = 0; n < 8; n++) {
                    uint32_t Bh[2], Bl[2];
                    ldsm_x2(Bh, addrWh + n * 8 * TSTR + k0 * 32);
                    ldsm_x2(Bl, addrWl + n * 8 * TSTR + k0 * 32);
                    mma_bf16(acc[n], Ah, Bh);
                    mma_bf16(acc[n], Ah, Bl);
                    mma_bf16(acc[n], Al, Bh);
                }
            }

            // ---- epilogue: p[j] = sum_kk relu(a2+ab1)*aw2 ----
            {
                float p0 = 0.f, p1 = 0.f;
#pragma unroll
                for (int n = 0; n < 8; n++) {
                    int kk = n * 8 + (lane & 3) * 2;
                    float b0 = s_ab1[kk], b1 = s_ab1[kk + 1];
                    float w0 = s_aw2[kk], w1 = s_aw2[kk + 1];
                    p0 += fmaxf(acc[n][0] + b0, 0.f) * w0
                        + fmaxf(acc[n][1] + b1, 0.f) * w1;
                    p1 += fmaxf(acc[n][2] + b0, 0.f) * w0
                        + fmaxf(acc[n][3] + b1, 0.f) * w1;
                }
                p0 += __shfl_xor_sync(0xffffffffu, p0, 1);
                p0 += __shfl_xor_sync(0xffffffffu, p0, 2);
                p1 += __shfl_xor_sync(0xffffffffu, p1, 1);
                p1 += __shfl_xor_sync(0xffffffffu, p1, 2);
                if ((lane & 3) == 0) {
                    int j0 = m0 + (lane >> 2);
                    s_A[i * 128 + j0]     = fmaxf(p0 + ab2v, 0.f);
                    s_A[i * 128 + j0 + 8] = fmaxf(p1 + ab2v, 0.f);
                }
            }
            __syncthreads();
        }

        // ---- V accumulation: 8 i-rows vs h tile (L2-resident) ----
        {
            const float* hp = g_h + (size_t)(b * NN + jt * 128) * 128 + c;
            const float* sA = s_A + half * 4 * 128;
#pragma unroll 4
            for (int j = 0; j < 128; j++) {
                float hv = __ldg(hp + (size_t)j * 128);
                Vacc[0] += sA[0 * 128 + j] * hv;
                Vacc[1] += sA[1 * 128 + j] * hv;
                Vacc[2] += sA[2 * 128 + j] * hv;
                Vacc[3] += sA[3 * 128 + j] * hv;
            }
        }
    }

    // write V into updates[:, 131:259)
#pragma unroll
    for (int x = 0; x < 4; x++)
        g_upd[(size_t)(b * NN + i0 + half * 4 + x) * 259 + 131 + c] = Vacc[x];
}

// ============================================================================
// Kernel 3: update MLP (259 -> 256 -> 128), 16 rows/CTA, 256 CTAs.
// ============================================================================
#define SMEM_UPD (2 * 16 * 260 * 4)

__global__ void __launch_bounds__(256) k_upd(
    const float* __restrict__ uw0, const float* __restrict__ ub0,
    const float* __restrict__ uw1, const float* __restrict__ ub1)
{
    extern __shared__ float smf[];
    float* s_upd = smf;             // 16 * 260
    float* s_mid = smf + 16 * 260;  // 16 * 260

    const int tid = threadIdx.x;
    const int r0 = blockIdx.x * 16;

    for (int idx = tid; idx < 16 * 259; idx += 256) {
        int r = idx / 259, cc = idx - r * 259;
        s_upd[r * 260 + cc] = g_upd[(size_t)(r0 + r) * 259 + cc];
    }
    __syncthreads();

    const int mg = tid & 31;
    const int rg = tid >> 5;   // 8 groups x 2 rows

    // GEMM1: (16x259) @ (259x256)
    {
        float acc[2][8];
#pragma unroll
        for (int x = 0; x < 2; x++)
#pragma unroll
            for (int q = 0; q < 8; q++) acc[x][q] = 0.f;

        for (int rr = 0; rr < 259; rr++) {
            float4 w0 = *(const float4*)&uw0[rr * 256 + mg * 8];
            float4 w1 = *(const float4*)&uw0[rr * 256 + mg * 8 + 4];
            float a0 = s_upd[(rg * 2 + 0) * 260 + rr];
            float a1 = s_upd[(rg * 2 + 1) * 260 + rr];
            float av[2] = {a0, a1};
#pragma unroll
            for (int x = 0; x < 2; x++) {
                acc[x][0] += av[x] * w0.x; acc[x][1] += av[x] * w0.y;
                acc[x][2] += av[x] * w0.z; acc[x][3] += av[x] * w0.w;
                acc[x][4] += av[x] * w1.x; acc[x][5] += av[x] * w1.y;
                acc[x][6] += av[x] * w1.z; acc[x][7] += av[x] * w1.w;
            }
        }
#pragma unroll
        for (int x = 0; x < 2; x++)
#pragma unroll
            for (int q = 0; q < 8; q++)
                s_mid[(rg * 2 + x) * 260 + mg * 8 + q] =
                    fmaxf(acc[x][q] + ub0[mg * 8 + q], 0.f);
    }
    __syncthreads();

    // GEMM2: (16x256) @ (256x128)
    {
        const int cg = tid & 31;
        float acc[2][4];
#pragma unroll
        for (int x = 0; x < 2; x++)
#pragma unroll
            for (int q = 0; q < 4; q++) acc[x][q] = 0.f;

        for (int mm = 0; mm < 256; mm++) {
            float4 w = *(const float4*)&uw1[mm * 128 + cg * 4];
            float av[2];
#pragma unroll
            for (int x = 0; x < 2; x++) av[x] = s_mid[(rg * 2 + x) * 260 + mm];
#pragma unroll
            for (int x = 0; x < 2; x++) {
                acc[x][0] += av[x] * w.x; acc[x][1] += av[x] * w.y;
                acc[x][2] += av[x] * w.z; acc[x][3] += av[x] * w.w;
            }
        }
#pragma unroll
        for (int x = 0; x < 2; x++) {
            float4 o;
            o.x = fmaxf(acc[x][0] + ub1[cg * 4 + 0], 0.f);
            o.y = fmaxf(acc[x][1] + ub1[cg * 4 + 1], 0.f);
            o.z = fmaxf(acc[x][2] + ub1[cg * 4 + 2], 0.f);
            o.w = fmaxf(acc[x][3] + ub1[cg * 4 + 3], 0.f);
            *(float4*)&g_hn[(size_t)(r0 + rg * 2 + x) * 128 + cg * 4] = o;
        }
    }
}

// ============================================================================
// Kernel 4: maxpool over N. grid 32 CTAs, 256 threads.
// ============================================================================
__global__ void k_pool(float* __restrict__ out)
{
    __shared__ float s[256];
    const int tid = threadIdx.x;
    const int b = blockIdx.x >> 2;
    const int c = ((blockIdx.x & 3) << 5) + (tid & 31);
    const int ng = tid >> 5;
    float m = -3.4e38f;
    for (int n = ng; n < NN; n += 8)
        m = fmaxf(m, g_hn[(size_t)(b * NN + n) * 128 + c]);
    s[tid] = m;
    __syncthreads();
    if (tid < 32) {
        float mm = s[tid];
#pragma unroll
        for (int g = 1; g < 8; g++) mm = fmaxf(mm, s[g * 32 + tid]);
        out[b * 128 + c] = mm;
    }
}

// ============================================================================
extern "C" void kernel_launch(void* const* d_in, const int* in_sizes, int n_in,
                              void* d_out, int out_size)
{
    const float* coords = (const float*)d_in[0];
    const float* fw0 = (const float*)d_in[1];
    const float* fb0 = (const float*)d_in[2];
    const float* fw1 = (const float*)d_in[3];
    const float* fb1 = (const float*)d_in[4];
    const float* aw0 = (const float*)d_in[5];
    const float* ab0 = (const float*)d_in[6];
    const float* aw1 = (const float*)d_in[7];
    const float* ab1 = (const float*)d_in[8];
    const float* aw2 = (const float*)d_in[9];
    const float* ab2 = (const float*)d_in[10];
    const float* uw0 = (const float*)d_in[11];
    const float* ub0 = (const float*)d_in[12];
    const float* uw1 = (const float*)d_in[13];
    const float* ub1 = (const float*)d_in[14];
    float* out = (float*)d_out;

    static int attr_set = 0;
    if (!attr_set) {
        cudaFuncSetAttribute(k_adj, cudaFuncAttributeMaxDynamicSharedMemorySize, SMEM_ADJ);
        attr_set = 1;
    }

    k_prep<<<16, 256>>>(aw1);
    k_feat<<<32, 128>>>(coords, fw0, fb0, fw1, fb1, aw0, ab0);
    k_adj<<<512, 256, SMEM_ADJ>>>(ab1, aw2, ab2);
    k_upd<<<256, 256, SMEM_UPD>>>(uw0, ub0, uw1, ub1);
    k_pool<<<32, 256>>>(out);
}